// round 1
// baseline (speedup 1.0000x reference)
#include <cuda_runtime.h>
#include <math.h>

#define BB 4
#define NN 512
#define FF 256   // in_f == out_f == 256
#define EE 64
#define TILE_I 8
#define LRELU_ALPHA 0.2f
#define NEG_INF_V -1e30f

// scratch (no allocations allowed)
__device__ float g_h[BB*NN*FF];      // 2 MB
__device__ float g_si[BB*NN];
__device__ float g_sj[BB*NN];
__device__ float g_w1a3[EE];

// ---------------- Kernel 1: h = x @ W  (2048x256x256 SGEMM, 64x64 tiles, 4x4 regs) ----
__global__ __launch_bounds__(256) void gemm_h_kernel(const float* __restrict__ X,
                                                     const float* __restrict__ Wm) {
    __shared__ float As[16][65];   // As[k][m]
    __shared__ float Bs[16][68];   // Bs[k][n], padded to keep float4 alignment
    const int bm = blockIdx.x * 64;
    const int bn = blockIdx.y * 64;
    const int tid = threadIdx.x;
    const int tx = tid & 15, ty = tid >> 4;
    float acc[4][4] = {};
    const int alr = tid >> 2;            // 0..63 row of A tile
    const int alc = (tid & 3) * 4;       // k offset within 16
    const int bkr = tid >> 4;            // 0..15 k row of B tile
    const int bnc = (tid & 15) * 4;      // 0..60 n offset

    for (int k0 = 0; k0 < FF; k0 += 16) {
        float4 xa = *(const float4*)&X[(bm + alr)*FF + k0 + alc];
        As[alc+0][alr] = xa.x; As[alc+1][alr] = xa.y;
        As[alc+2][alr] = xa.z; As[alc+3][alr] = xa.w;
        float4 wb = *(const float4*)&Wm[(k0 + bkr)*FF + bn + bnc];
        *(float4*)&Bs[bkr][bnc] = wb;
        __syncthreads();
        #pragma unroll
        for (int k = 0; k < 16; k++) {
            float ra[4];
            #pragma unroll
            for (int i = 0; i < 4; i++) ra[i] = As[k][ty*4+i];
            float4 rb = *(const float4*)&Bs[k][tx*4];
            #pragma unroll
            for (int i = 0; i < 4; i++) {
                acc[i][0] += ra[i]*rb.x;
                acc[i][1] += ra[i]*rb.y;
                acc[i][2] += ra[i]*rb.z;
                acc[i][3] += ra[i]*rb.w;
            }
        }
        __syncthreads();
    }
    #pragma unroll
    for (int i = 0; i < 4; i++) {
        float4 o = make_float4(acc[i][0], acc[i][1], acc[i][2], acc[i][3]);
        *(float4*)&g_h[(bm + ty*4 + i)*FF + bn + tx*4] = o;
    }
}

// ---------------- Kernel 2: s_i[row] = h[row]·a1, s_j[row] = h[row]·a2 ----------------
__global__ __launch_bounds__(256) void aux_kernel(const float* __restrict__ a) {
    const int wid  = threadIdx.x >> 5;
    const int lane = threadIdx.x & 31;
    const int row  = blockIdx.x * 8 + wid;
    float p1 = 0.f, p2 = 0.f;
    #pragma unroll
    for (int c = lane; c < FF; c += 32) {
        float hv = g_h[row*FF + c];
        p1 += hv * __ldg(&a[c]);
        p2 += hv * __ldg(&a[FF + c]);
    }
    #pragma unroll
    for (int o = 16; o > 0; o >>= 1) {
        p1 += __shfl_xor_sync(0xffffffffu, p1, o);
        p2 += __shfl_xor_sync(0xffffffffu, p2, o);
    }
    if (lane == 0) { g_si[row] = p1; g_sj[row] = p2; }
}

// ---------------- Kernel 3: w1a3[e] = W1[e,:]·a3 ----------------
__global__ void w1a3_kernel(const float* __restrict__ W1, const float* __restrict__ a) {
    const int wid  = threadIdx.x >> 5;
    const int lane = threadIdx.x & 31;
    const int e = blockIdx.x * 32 + wid;
    if (e >= EE) return;
    float p = 0.f;
    #pragma unroll
    for (int c = lane; c < FF; c += 32)
        p += W1[e*FF + c] * __ldg(&a[2*FF + c]);
    #pragma unroll
    for (int o = 16; o > 0; o >>= 1)
        p += __shfl_xor_sync(0xffffffffu, p, o);
    if (lane == 0) g_w1a3[e] = p;
}

// ---------------- Kernel 4: fused score + mask + softmax + attn@h + elu ----------------
// One CTA handles TILE_I=8 query rows (b, i0..i0+7). 256 threads.
__global__ __launch_bounds__(256) void attn_kernel(const float* __restrict__ edge,
                                                   const float* __restrict__ adj,
                                                   float* __restrict__ out) {
    __shared__ float sh_sj[NN];
    __shared__ float sh_w[EE];
    __shared__ float sh_attn[TILE_I][NN];
    __shared__ float red_max[8];
    __shared__ float red_sum[8];

    const int tid = threadIdx.x;
    const int b  = blockIdx.x / (NN / TILE_I);
    const int i0 = (blockIdx.x % (NN / TILE_I)) * TILE_I;

    sh_sj[tid]       = g_sj[b*NN + tid];
    sh_sj[tid + 256] = g_sj[b*NN + tid + 256];
    if (tid < EE) sh_w[tid] = g_w1a3[tid];
    __syncthreads();

    // ---- phase 1: scores e[r][j] = lrelu(s_i + s_j + edge[b,i,j,:]·w1a3) ----
    // 16 lanes per j, float4 per lane -> 256B contiguous per j, fully coalesced.
    const int g = tid >> 4;
    const int l = tid & 15;
    const float4 wv = *(const float4*)&sh_w[l*4];

    #pragma unroll
    for (int r = 0; r < TILE_I; r++) {
        const int i = i0 + r;
        const float si = g_si[b*NN + i];
        const float4* erow = (const float4*)(edge + (size_t)(b*NN + i) * NN * EE);
        #pragma unroll 4
        for (int jt = g; jt < NN; jt += 16) {
            float4 ev = erow[jt*16 + l];
            float p = ev.x*wv.x + ev.y*wv.y + ev.z*wv.z + ev.w*wv.w;
            p += __shfl_xor_sync(0xffffffffu, p, 8);
            p += __shfl_xor_sync(0xffffffffu, p, 4);
            p += __shfl_xor_sync(0xffffffffu, p, 2);
            p += __shfl_xor_sync(0xffffffffu, p, 1);
            if (l == 0) {
                float e = si + sh_sj[jt] + p;
                sh_attn[r][jt] = (e >= 0.f) ? e : LRELU_ALPHA * e;
            }
        }
    }
    __syncthreads();

    // ---- phase 2: mask + softmax over j (in place in sh_attn) ----
    const int lane = tid & 31;
    const int wid  = tid >> 5;
    for (int r = 0; r < TILE_I; r++) {
        const float* arow = adj + (size_t)(b*NN + i0 + r) * NN;
        float v0 = sh_attn[r][tid];
        float v1 = sh_attn[r][tid + 256];
        v0 = (arow[tid]       > 0.f) ? v0 : NEG_INF_V;
        v1 = (arow[tid + 256] > 0.f) ? v1 : NEG_INF_V;

        float m = fmaxf(v0, v1);
        #pragma unroll
        for (int o = 16; o > 0; o >>= 1) m = fmaxf(m, __shfl_xor_sync(0xffffffffu, m, o));
        if (lane == 0) red_max[wid] = m;
        __syncthreads();
        float bmax = red_max[0];
        #pragma unroll
        for (int w = 1; w < 8; w++) bmax = fmaxf(bmax, red_max[w]);

        float e0 = __expf(v0 - bmax);
        float e1 = __expf(v1 - bmax);
        float s = e0 + e1;
        #pragma unroll
        for (int o = 16; o > 0; o >>= 1) s += __shfl_xor_sync(0xffffffffu, s, o);
        if (lane == 0) red_sum[wid] = s;
        __syncthreads();
        float bsum = red_sum[0];
        #pragma unroll
        for (int w = 1; w < 8; w++) bsum += red_sum[w];

        float inv = 1.f / bsum;
        sh_attn[r][tid]       = e0 * inv;
        sh_attn[r][tid + 256] = e1 * inv;
        __syncthreads();
    }

    // ---- phase 3: h_prime[r][tid] = sum_j attn[r][j] * h[b,j,tid]; then elu ----
    float acc[TILE_I] = {};
    const float* hb = g_h + (size_t)b * NN * FF;
    for (int jt = 0; jt < NN; jt += 4) {
        float4 av[TILE_I];
        #pragma unroll
        for (int r = 0; r < TILE_I; r++) av[r] = *(const float4*)&sh_attn[r][jt];
        #pragma unroll
        for (int u = 0; u < 4; u++) {
            float hv = hb[(jt + u)*FF + tid];
            #pragma unroll
            for (int r = 0; r < TILE_I; r++) {
                float a = (u == 0) ? av[r].x : (u == 1) ? av[r].y : (u == 2) ? av[r].z : av[r].w;
                acc[r] += a * hv;
            }
        }
    }
    #pragma unroll
    for (int r = 0; r < TILE_I; r++) {
        float v = acc[r];
        out[(size_t)(b*NN + i0 + r)*FF + tid] = (v > 0.f) ? v : expm1f(v);
    }
}

// ---------------- launcher ----------------
extern "C" void kernel_launch(void* const* d_in, const int* in_sizes, int n_in,
                              void* d_out, int out_size) {
    const float* x    = (const float*)d_in[0];  // [4,512,256]
    const float* edge = (const float*)d_in[1];  // [4,512,512,64]
    const float* adj  = (const float*)d_in[2];  // [4,512,512]
    const float* W    = (const float*)d_in[3];  // [256,256]
    const float* W1   = (const float*)d_in[4];  // [64,256]
    const float* a    = (const float*)d_in[5];  // [768,1]
    float* out = (float*)d_out;                 // [4,512,256]

    dim3 ggrid(BB*NN/64, FF/64);
    gemm_h_kernel<<<ggrid, 256>>>(x, W);
    aux_kernel<<<BB*NN/8, 256>>>(a);
    w1a3_kernel<<<2, 1024>>>(W1, a);
    attn_kernel<<<BB*NN/TILE_I, 256>>>(edge, adj, out);
}

// round 2
// speedup vs baseline: 1.9124x; 1.9124x over previous
#include <cuda_runtime.h>
#include <math.h>

#define BB 4
#define NN 512
#define FF 256
#define EE 64
#define TILE_I 8
#define LRELU_ALPHA 0.2f
#define NEG_INF_V -1e30f

// scratch (no allocations allowed)
__device__ float g_h[BB*NN*FF];      // 2 MB
__device__ float g_si[BB*NN];
__device__ float g_sj[BB*NN];
__device__ float g_w1a3[EE];
__device__ float g_sc[BB*NN*NN];     // 4 MB raw edge scores

// ---- f32x2 packed helpers (Blackwell FFMA2) ----
__device__ __forceinline__ unsigned long long ffma2(unsigned long long a,
                                                    unsigned long long b,
                                                    unsigned long long c) {
    unsigned long long d;
    asm("fma.rn.f32x2 %0, %1, %2, %3;" : "=l"(d) : "l"(a), "l"(b), "l"(c));
    return d;
}
__device__ __forceinline__ unsigned long long pack2(float lo, float hi) {
    unsigned long long d;
    asm("mov.b64 %0, {%1, %2};" : "=l"(d) : "f"(lo), "f"(hi));
    return d;
}
__device__ __forceinline__ void unpack2(unsigned long long v, float& lo, float& hi) {
    asm("mov.b64 {%0, %1}, %2;" : "=f"(lo), "=f"(hi) : "l"(v));
}

// ================= Kernel 1: h = x @ W (f32x2, 32x64 tiles, 256 CTAs) =================
__global__ __launch_bounds__(256) void gemm_h_kernel(const float* __restrict__ X,
                                                     const float* __restrict__ Wm) {
    __shared__ __align__(16) float As[16][33];   // [k][m]
    __shared__ __align__(16) float Bs[16][68];   // [k][n]
    const int bm = blockIdx.x * 32;
    const int bn = blockIdx.y * 64;
    const int tid = threadIdx.x;
    const int tx = tid & 15;        // n group: 4 floats
    const int ty = tid >> 4;        // m group: 2 rows
    const int ar = tid >> 3;        // A row 0..31
    const int ac = (tid & 7) * 2;   // A col (k) 0..14
    const int br = tid >> 4;        // B k-row 0..15
    const int bc = (tid & 15) * 4;  // B n 0..60

    unsigned long long acc00 = 0, acc01 = 0, acc10 = 0, acc11 = 0;

    for (int k0 = 0; k0 < FF; k0 += 16) {
        float2 xa = *(const float2*)&X[(size_t)(bm + ar)*FF + k0 + ac];
        As[ac][ar] = xa.x; As[ac+1][ar] = xa.y;
        *(float4*)&Bs[br][bc] = *(const float4*)&Wm[(size_t)(k0 + br)*FF + bn + bc];
        __syncthreads();
        #pragma unroll
        for (int k = 0; k < 16; k++) {
            float a0 = As[k][ty*2+0];
            float a1 = As[k][ty*2+1];
            unsigned long long a0d = pack2(a0, a0);
            unsigned long long a1d = pack2(a1, a1);
            ulonglong2 bq = *(const ulonglong2*)&Bs[k][tx*4];
            acc00 = ffma2(a0d, bq.x, acc00);
            acc01 = ffma2(a0d, bq.y, acc01);
            acc10 = ffma2(a1d, bq.x, acc10);
            acc11 = ffma2(a1d, bq.y, acc11);
        }
        __syncthreads();
    }
    float c0, c1, c2, c3;
    unpack2(acc00, c0, c1); unpack2(acc01, c2, c3);
    *(float4*)&g_h[(size_t)(bm + ty*2 + 0)*FF + bn + tx*4] = make_float4(c0, c1, c2, c3);
    unpack2(acc10, c0, c1); unpack2(acc11, c2, c3);
    *(float4*)&g_h[(size_t)(bm + ty*2 + 1)*FF + bn + tx*4] = make_float4(c0, c1, c2, c3);
}

// ================= Kernel 2: s_i / s_j row dots =================
__global__ __launch_bounds__(256) void aux_kernel(const float* __restrict__ a) {
    const int wid  = threadIdx.x >> 5;
    const int lane = threadIdx.x & 31;
    const int row  = blockIdx.x * 8 + wid;
    float p1 = 0.f, p2 = 0.f;
    #pragma unroll
    for (int c = lane; c < FF; c += 32) {
        float hv = g_h[(size_t)row*FF + c];
        p1 += hv * __ldg(&a[c]);
        p2 += hv * __ldg(&a[FF + c]);
    }
    #pragma unroll
    for (int o = 16; o > 0; o >>= 1) {
        p1 += __shfl_xor_sync(0xffffffffu, p1, o);
        p2 += __shfl_xor_sync(0xffffffffu, p2, o);
    }
    if (lane == 0) { g_si[row] = p1; g_sj[row] = p2; }
}

// ================= Kernel 3: w1a3[e] = W1[e,:]·a3 =================
__global__ void w1a3_kernel(const float* __restrict__ W1, const float* __restrict__ a) {
    const int wid  = threadIdx.x >> 5;
    const int lane = threadIdx.x & 31;
    const int e = blockIdx.x * 32 + wid;
    if (e >= EE) return;
    float p = 0.f;
    #pragma unroll
    for (int c = lane; c < FF; c += 32)
        p += W1[(size_t)e*FF + c] * __ldg(&a[2*FF + c]);
    #pragma unroll
    for (int o = 16; o > 0; o >>= 1)
        p += __shfl_xor_sync(0xffffffffu, p, o);
    if (lane == 0) g_w1a3[e] = p;
}

// ================= Kernel 4: raw edge scores (the 268 MB stream) =================
// One CTA per (b,i). 8 warps; warp w owns j in [w*64, w*64+64).
// 16 lanes per j -> 256B contiguous per j, 512B per warp-wide LDG.128.
__global__ __launch_bounds__(256) void score_kernel(const float* __restrict__ edge) {
    __shared__ float s_w[EE];
    __shared__ float s_sc[NN];
    const int tid = threadIdx.x;
    const int bi  = blockIdx.x;               // b*NN + i
    if (tid < EE) s_w[tid] = g_w1a3[tid];
    __syncthreads();

    const int w = tid >> 5;
    const int lane = tid & 31;
    const int g = lane >> 4;                  // 0/1: which j of the pair
    const int l = lane & 15;
    const float4 wv = *(const float4*)&s_w[l*4];
    const float4* erow = (const float4*)(edge + (size_t)bi * NN * EE);
    const int jw = w * 64;

    #pragma unroll
    for (int t = 0; t < 8; t++) {
        const int jb = jw + t*8 + g;
        float4 ev[4];
        #pragma unroll
        for (int u = 0; u < 4; u++)
            ev[u] = erow[(size_t)(jb + 2*u)*16 + l];
        #pragma unroll
        for (int u = 0; u < 4; u++) {
            float p = ev[u].x*wv.x + ev[u].y*wv.y + ev[u].z*wv.z + ev[u].w*wv.w;
            p += __shfl_xor_sync(0xffffffffu, p, 8);
            p += __shfl_xor_sync(0xffffffffu, p, 4);
            p += __shfl_xor_sync(0xffffffffu, p, 2);
            p += __shfl_xor_sync(0xffffffffu, p, 1);
            if (l == 0) s_sc[jb + 2*u] = p;
        }
    }
    __syncthreads();
    *(float2*)&g_sc[(size_t)bi*NN + tid*2] = *(const float2*)&s_sc[tid*2];
}

// ================= Kernel 5: lrelu+mask+softmax + attn@h (f32x2) + elu =================
// One CTA per (b, 8-row tile). 512 threads: softmax phase = one j per thread;
// AV phase = (j-half, f) with row-pair-packed FFMA2.
__global__ __launch_bounds__(512) void softmax_av_kernel(const float* __restrict__ adj,
                                                         float* __restrict__ out) {
    __shared__ __align__(16) float2 sh_ap[TILE_I/2][NN];  // packed (r,r+1) attn, 16KB
    __shared__ float redm[TILE_I][16];
    __shared__ float reds[TILE_I][16];

    const int tid = threadIdx.x;
    const int b  = blockIdx.x / (NN / TILE_I);
    const int i0 = (blockIdx.x % (NN / TILE_I)) * TILE_I;
    const int lane = tid & 31;
    const int wid  = tid >> 5;

    // ---- softmax: thread owns column j = tid across all 8 rows ----
    const float sj = g_sj[b*NN + tid];
    float v[TILE_I];
    const float* scb  = g_sc + (size_t)(b*NN + i0)*NN;
    const float* adjb = adj  + (size_t)(b*NN + i0)*NN;
    #pragma unroll
    for (int r = 0; r < TILE_I; r++) {
        float e = g_si[b*NN + i0 + r] + sj + scb[(size_t)r*NN + tid];
        e = (e >= 0.f) ? e : LRELU_ALPHA * e;
        v[r] = (adjb[(size_t)r*NN + tid] > 0.f) ? e : NEG_INF_V;
    }
    float m[TILE_I];
    #pragma unroll
    for (int r = 0; r < TILE_I; r++) {
        m[r] = v[r];
        #pragma unroll
        for (int o = 16; o > 0; o >>= 1)
            m[r] = fmaxf(m[r], __shfl_xor_sync(0xffffffffu, m[r], o));
    }
    if (lane == 0) {
        #pragma unroll
        for (int r = 0; r < TILE_I; r++) redm[r][wid] = m[r];
    }
    __syncthreads();
    float ev[TILE_I], s[TILE_I];
    #pragma unroll
    for (int r = 0; r < TILE_I; r++) {
        float bm = redm[r][0];
        #pragma unroll
        for (int wq = 1; wq < 16; wq++) bm = fmaxf(bm, redm[r][wq]);
        ev[r] = __expf(v[r] - bm);
        s[r] = ev[r];
        #pragma unroll
        for (int o = 16; o > 0; o >>= 1)
            s[r] += __shfl_xor_sync(0xffffffffu, s[r], o);
    }
    if (lane == 0) {
        #pragma unroll
        for (int r = 0; r < TILE_I; r++) reds[r][wid] = s[r];
    }
    __syncthreads();
    #pragma unroll
    for (int rp = 0; rp < TILE_I/2; rp++) {
        float s0 = 0.f, s1 = 0.f;
        #pragma unroll
        for (int wq = 0; wq < 16; wq++) { s0 += reds[2*rp][wq]; s1 += reds[2*rp+1][wq]; }
        sh_ap[rp][tid] = make_float2(ev[2*rp] / s0, ev[2*rp+1] / s1);
    }
    __syncthreads();

    // ---- attn @ h with row-pair packed FFMA2 ----
    const int half = tid >> 8;
    const int f = tid & 255;
    unsigned long long acc[TILE_I/2] = {0ull, 0ull, 0ull, 0ull};
    const float* hb = g_h + (size_t)b*NN*FF;

    for (int jt = half*256; jt < half*256 + 256; jt += 8) {
        float hv[8];
        #pragma unroll
        for (int u = 0; u < 8; u++) hv[u] = hb[(size_t)(jt + u)*FF + f];
        unsigned long long hd[8];
        #pragma unroll
        for (int u = 0; u < 8; u++) hd[u] = pack2(hv[u], hv[u]);
        #pragma unroll
        for (int rp = 0; rp < TILE_I/2; rp++) {
            ulonglong2 q0 = *(const ulonglong2*)&sh_ap[rp][jt + 0];
            ulonglong2 q1 = *(const ulonglong2*)&sh_ap[rp][jt + 2];
            ulonglong2 q2 = *(const ulonglong2*)&sh_ap[rp][jt + 4];
            ulonglong2 q3 = *(const ulonglong2*)&sh_ap[rp][jt + 6];
            acc[rp] = ffma2(q0.x, hd[0], acc[rp]);
            acc[rp] = ffma2(q0.y, hd[1], acc[rp]);
            acc[rp] = ffma2(q1.x, hd[2], acc[rp]);
            acc[rp] = ffma2(q1.y, hd[3], acc[rp]);
            acc[rp] = ffma2(q2.x, hd[4], acc[rp]);
            acc[rp] = ffma2(q2.y, hd[5], acc[rp]);
            acc[rp] = ffma2(q3.x, hd[6], acc[rp]);
            acc[rp] = ffma2(q3.y, hd[7], acc[rp]);
        }
    }

    // combine halves, ELU, store
    __syncthreads();
    if (half == 1) {
        #pragma unroll
        for (int rp = 0; rp < TILE_I/2; rp++) {
            float lo, hi; unpack2(acc[rp], lo, hi);
            sh_ap[rp][f] = make_float2(lo, hi);
        }
    }
    __syncthreads();
    if (half == 0) {
        #pragma unroll
        for (int rp = 0; rp < TILE_I/2; rp++) {
            float lo, hi; unpack2(acc[rp], lo, hi);
            float2 o = sh_ap[rp][f];
            float v0 = lo + o.x;
            float v1 = hi + o.y;
            out[(size_t)(b*NN + i0 + 2*rp + 0)*FF + f] = (v0 > 0.f) ? v0 : expm1f(v0);
            out[(size_t)(b*NN + i0 + 2*rp + 1)*FF + f] = (v1 > 0.f) ? v1 : expm1f(v1);
        }
    }
}

// ================= launcher =================
extern "C" void kernel_launch(void* const* d_in, const int* in_sizes, int n_in,
                              void* d_out, int out_size) {
    const float* x    = (const float*)d_in[0];  // [4,512,256]
    const float* edge = (const float*)d_in[1];  // [4,512,512,64]
    const float* adj  = (const float*)d_in[2];  // [4,512,512]
    const float* W    = (const float*)d_in[3];  // [256,256]
    const float* W1   = (const float*)d_in[4];  // [64,256]
    const float* a    = (const float*)d_in[5];  // [768,1]
    float* out = (float*)d_out;                 // [4,512,256]

    w1a3_kernel<<<2, 1024>>>(W1, a);
    score_kernel<<<BB*NN, 256>>>(edge);
    dim3 ggrid(BB*NN/32, FF/64);
    gemm_h_kernel<<<ggrid, 256>>>(x, W);
    aux_kernel<<<BB*NN/8, 256>>>(a);
    softmax_av_kernel<<<BB*NN/TILE_I, 512>>>(adj, out);
}

// round 3
// speedup vs baseline: 2.2443x; 1.1736x over previous
#include <cuda_runtime.h>
#include <math.h>

#define BB 4
#define NN 512
#define FF 256
#define EE 64
#define TILE_I 16
#define LRELU_ALPHA 0.2f
#define NEG_INF_V -1e30f

#define GEMM_CTAS 256   // 64 m-tiles x 4 n-tiles

// scratch (no allocations allowed)
__device__ float g_h[BB*NN*FF];        // 2 MB
__device__ float g_sip[4*BB*NN];       // per-n-tile partial s_i
__device__ float g_sjp[4*BB*NN];       // per-n-tile partial s_j
__device__ float g_w1a3[EE];
__device__ float g_sc[BB*NN*NN];       // 4 MB raw edge scores

// ---- f32x2 packed helpers (Blackwell FFMA2) ----
__device__ __forceinline__ unsigned long long ffma2(unsigned long long a,
                                                    unsigned long long b,
                                                    unsigned long long c) {
    unsigned long long d;
    asm("fma.rn.f32x2 %0, %1, %2, %3;" : "=l"(d) : "l"(a), "l"(b), "l"(c));
    return d;
}
__device__ __forceinline__ unsigned long long pack2(float lo, float hi) {
    unsigned long long d;
    asm("mov.b64 %0, {%1, %2};" : "=l"(d) : "f"(lo), "f"(hi));
    return d;
}
__device__ __forceinline__ void unpack2(unsigned long long v, float& lo, float& hi) {
    asm("mov.b64 {%0, %1}, %2;" : "=f"(lo), "=f"(hi) : "l"(v));
}

// ================= Kernel 0: w1a3[e] = W1[e,:]·a3 =================
__global__ void w1a3_kernel(const float* __restrict__ W1, const float* __restrict__ a) {
    const int wid  = threadIdx.x >> 5;
    const int lane = threadIdx.x & 31;
    const int e = blockIdx.x * 32 + wid;
    if (e >= EE) return;
    float p = 0.f;
    #pragma unroll
    for (int c = lane; c < FF; c += 32)
        p += W1[(size_t)e*FF + c] * __ldg(&a[2*FF + c]);
    #pragma unroll
    for (int o = 16; o > 0; o >>= 1)
        p += __shfl_xor_sync(0xffffffffu, p, o);
    if (lane == 0) g_w1a3[e] = p;
}

// ================= Kernel 1: MEGA — gemm(+si/sj partials) overlapped with edge scoring =====
// bid < GEMM_CTAS           : h = x@W 32x64 tile; epilogue writes si/sj partial dots
// bid in [GEMM_CTAS, +2048) : score row bi = bid - GEMM_CTAS (the 268MB DRAM stream)
__global__ __launch_bounds__(256) void mega_kernel(const float* __restrict__ X,
                                                   const float* __restrict__ Wm,
                                                   const float* __restrict__ edge,
                                                   const float* __restrict__ a) {
    __shared__ __align__(16) float As[16][33];   // gemm path
    __shared__ __align__(16) float Bs[16][68];
    __shared__ float s_w[EE];                    // score path
    __shared__ float s_sc[NN];

    const int tid = threadIdx.x;

    if (blockIdx.x < GEMM_CTAS) {
        // ---------------- GEMM path ----------------
        const int bmi = blockIdx.x & 63;
        const int bni = blockIdx.x >> 6;
        const int bm = bmi * 32;
        const int bn = bni * 64;
        const int tx = tid & 15;
        const int ty = tid >> 4;
        const int ar = tid >> 3;
        const int ac = (tid & 7) * 2;
        const int br = tid >> 4;
        const int bc = (tid & 15) * 4;

        unsigned long long acc00 = 0, acc01 = 0, acc10 = 0, acc11 = 0;
        for (int k0 = 0; k0 < FF; k0 += 16) {
            float2 xa = *(const float2*)&X[(size_t)(bm + ar)*FF + k0 + ac];
            As[ac][ar] = xa.x; As[ac+1][ar] = xa.y;
            *(float4*)&Bs[br][bc] = *(const float4*)&Wm[(size_t)(k0 + br)*FF + bn + bc];
            __syncthreads();
            #pragma unroll
            for (int k = 0; k < 16; k++) {
                float a0 = As[k][ty*2+0];
                float a1 = As[k][ty*2+1];
                unsigned long long a0d = pack2(a0, a0);
                unsigned long long a1d = pack2(a1, a1);
                ulonglong2 bq = *(const ulonglong2*)&Bs[k][tx*4];
                acc00 = ffma2(a0d, bq.x, acc00);
                acc01 = ffma2(a0d, bq.y, acc01);
                acc10 = ffma2(a1d, bq.x, acc10);
                acc11 = ffma2(a1d, bq.y, acc11);
            }
            __syncthreads();
        }
        float c00, c01, c02, c03, c10, c11, c12, c13;
        unpack2(acc00, c00, c01); unpack2(acc01, c02, c03);
        unpack2(acc10, c10, c11); unpack2(acc11, c12, c13);
        *(float4*)&g_h[(size_t)(bm + ty*2 + 0)*FF + bn + tx*4] = make_float4(c00, c01, c02, c03);
        *(float4*)&g_h[(size_t)(bm + ty*2 + 1)*FF + bn + tx*4] = make_float4(c10, c11, c12, c13);

        // epilogue: partial s_i/s_j over this n-tile
        const float4 a1v = *(const float4*)&a[bn + tx*4];
        const float4 a2v = *(const float4*)&a[FF + bn + tx*4];
        float pi0 = c00*a1v.x + c01*a1v.y + c02*a1v.z + c03*a1v.w;
        float pi1 = c10*a1v.x + c11*a1v.y + c12*a1v.z + c13*a1v.w;
        float pj0 = c00*a2v.x + c01*a2v.y + c02*a2v.z + c03*a2v.w;
        float pj1 = c10*a2v.x + c11*a2v.y + c12*a2v.z + c13*a2v.w;
        #pragma unroll
        for (int o = 8; o > 0; o >>= 1) {
            pi0 += __shfl_xor_sync(0xffffffffu, pi0, o);
            pi1 += __shfl_xor_sync(0xffffffffu, pi1, o);
            pj0 += __shfl_xor_sync(0xffffffffu, pj0, o);
            pj1 += __shfl_xor_sync(0xffffffffu, pj1, o);
        }
        if (tx == 0) {
            g_sip[bni*(BB*NN) + bm + ty*2 + 0] = pi0;
            g_sip[bni*(BB*NN) + bm + ty*2 + 1] = pi1;
            g_sjp[bni*(BB*NN) + bm + ty*2 + 0] = pj0;
            g_sjp[bni*(BB*NN) + bm + ty*2 + 1] = pj1;
        }
    } else {
        // ---------------- SCORE path (268 MB edge stream) ----------------
        const int bi = blockIdx.x - GEMM_CTAS;          // b*NN + i
        if (tid < EE) s_w[tid] = g_w1a3[tid];
        __syncthreads();

        const int w = tid >> 5;
        const int lane = tid & 31;
        const int g = lane >> 4;
        const int l = lane & 15;
        const float4 wv = *(const float4*)&s_w[l*4];
        const float4* erow = (const float4*)(edge + (size_t)bi * NN * EE);
        const int jw = w * 64;

        #pragma unroll
        for (int t = 0; t < 8; t++) {
            const int jb = jw + t*8 + g;
            float4 ev[4];
            #pragma unroll
            for (int u = 0; u < 4; u++)
                ev[u] = erow[(size_t)(jb + 2*u)*16 + l];
            #pragma unroll
            for (int u = 0; u < 4; u++) {
                float p = ev[u].x*wv.x + ev[u].y*wv.y + ev[u].z*wv.z + ev[u].w*wv.w;
                p += __shfl_xor_sync(0xffffffffu, p, 8);
                p += __shfl_xor_sync(0xffffffffu, p, 4);
                p += __shfl_xor_sync(0xffffffffu, p, 2);
                p += __shfl_xor_sync(0xffffffffu, p, 1);
                if (l == 0) s_sc[jb + 2*u] = p;
            }
        }
        __syncthreads();
        *(float2*)&g_sc[(size_t)bi*NN + tid*2] = *(const float2*)&s_sc[tid*2];
    }
}

// ================= Kernel 2: lrelu+mask+softmax + attn@h (f32x2) + elu; TILE_I=16 =========
__global__ __launch_bounds__(512) void softmax_av_kernel(const float* __restrict__ adj,
                                                         float* __restrict__ out) {
    __shared__ __align__(16) float2 sh_ap[TILE_I/2][NN];  // packed (2r,2r+1) attn, 32KB
    __shared__ float redm[TILE_I][16];
    __shared__ float reds[TILE_I][16];
    __shared__ float s_si[TILE_I];

    const int tid = threadIdx.x;
    const int b  = blockIdx.x >> 5;
    const int i0 = (blockIdx.x & 31) * TILE_I;
    const int lane = tid & 31;
    const int wid  = tid >> 5;

    if (tid < TILE_I) {
        float s = 0.f;
        #pragma unroll
        for (int t = 0; t < 4; t++) s += g_sip[t*(BB*NN) + b*NN + i0 + tid];
        s_si[tid] = s;
    }
    // s_j[b, j=tid]: sum of 4 partials
    float sj = 0.f;
    #pragma unroll
    for (int t = 0; t < 4; t++) sj += g_sjp[t*(BB*NN) + b*NN + tid];
    __syncthreads();

    // ---- masked lrelu scores for 16 rows, column j = tid ----
    float v[TILE_I];
    const float* scb  = g_sc + (size_t)(b*NN + i0)*NN;
    const float* adjb = adj  + (size_t)(b*NN + i0)*NN;
    #pragma unroll
    for (int r = 0; r < TILE_I; r++) {
        float e = s_si[r] + sj + scb[(size_t)r*NN + tid];
        e = (e >= 0.f) ? e : LRELU_ALPHA * e;
        v[r] = (adjb[(size_t)r*NN + tid] > 0.f) ? e : NEG_INF_V;
    }
    // ---- row max ----
    #pragma unroll
    for (int r = 0; r < TILE_I; r++) {
        float m = v[r];
        #pragma unroll
        for (int o = 16; o > 0; o >>= 1)
            m = fmaxf(m, __shfl_xor_sync(0xffffffffu, m, o));
        if (lane == 0) redm[r][wid] = m;
    }
    __syncthreads();
    // ---- exp + row sum ----
    #pragma unroll
    for (int r = 0; r < TILE_I; r++) {
        float bm = redm[r][0];
        #pragma unroll
        for (int wq = 1; wq < 16; wq++) bm = fmaxf(bm, redm[r][wq]);
        v[r] = __expf(v[r] - bm);
        float s = v[r];
        #pragma unroll
        for (int o = 16; o > 0; o >>= 1)
            s += __shfl_xor_sync(0xffffffffu, s, o);
        if (lane == 0) reds[r][wid] = s;
    }
    __syncthreads();
    #pragma unroll
    for (int rp = 0; rp < TILE_I/2; rp++) {
        float s0 = 0.f, s1 = 0.f;
        #pragma unroll
        for (int wq = 0; wq < 16; wq++) { s0 += reds[2*rp][wq]; s1 += reds[2*rp+1][wq]; }
        sh_ap[rp][tid] = make_float2(v[2*rp] / s0, v[2*rp+1] / s1);
    }
    __syncthreads();

    // ---- attn @ h with row-pair packed FFMA2; warp = 32 consecutive f (attn broadcast) ----
    const int half = tid >> 8;
    const int f = tid & 255;
    unsigned long long acc[TILE_I/2] = {};
    const float* hb = g_h + (size_t)b*NN*FF;

    for (int jt = half*256; jt < half*256 + 256; jt += 8) {
        float hv[8];
        #pragma unroll
        for (int u = 0; u < 8; u++) hv[u] = hb[(size_t)(jt + u)*FF + f];
        unsigned long long hd[8];
        #pragma unroll
        for (int u = 0; u < 8; u++) hd[u] = pack2(hv[u], hv[u]);
        #pragma unroll
        for (int rp = 0; rp < TILE_I/2; rp++) {
            ulonglong2 q0 = *(const ulonglong2*)&sh_ap[rp][jt + 0];
            ulonglong2 q1 = *(const ulonglong2*)&sh_ap[rp][jt + 2];
            ulonglong2 q2 = *(const ulonglong2*)&sh_ap[rp][jt + 4];
            ulonglong2 q3 = *(const ulonglong2*)&sh_ap[rp][jt + 6];
            acc[rp] = ffma2(q0.x, hd[0], acc[rp]);
            acc[rp] = ffma2(q0.y, hd[1], acc[rp]);
            acc[rp] = ffma2(q1.x, hd[2], acc[rp]);
            acc[rp] = ffma2(q1.y, hd[3], acc[rp]);
            acc[rp] = ffma2(q2.x, hd[4], acc[rp]);
            acc[rp] = ffma2(q2.y, hd[5], acc[rp]);
            acc[rp] = ffma2(q3.x, hd[6], acc[rp]);
            acc[rp] = ffma2(q3.y, hd[7], acc[rp]);
        }
    }

    // combine halves via smem (attn region is dead now), ELU, store
    __syncthreads();
    if (half == 1) {
        #pragma unroll
        for (int rp = 0; rp < TILE_I/2; rp++) {
            float lo, hi; unpack2(acc[rp], lo, hi);
            sh_ap[rp][f] = make_float2(lo, hi);
        }
    }
    __syncthreads();
    if (half == 0) {
        #pragma unroll
        for (int rp = 0; rp < TILE_I/2; rp++) {
            float lo, hi; unpack2(acc[rp], lo, hi);
            float2 o = sh_ap[rp][f];
            float v0 = lo + o.x;
            float v1 = hi + o.y;
            out[(size_t)(b*NN + i0 + 2*rp + 0)*FF + f] = (v0 > 0.f) ? v0 : expm1f(v0);
            out[(size_t)(b*NN + i0 + 2*rp + 1)*FF + f] = (v1 > 0.f) ? v1 : expm1f(v1);
        }
    }
}

// ================= launcher =================
extern "C" void kernel_launch(void* const* d_in, const int* in_sizes, int n_in,
                              void* d_out, int out_size) {
    const float* x    = (const float*)d_in[0];  // [4,512,256]
    const float* edge = (const float*)d_in[1];  // [4,512,512,64]
    const float* adj  = (const float*)d_in[2];  // [4,512,512]
    const float* W    = (const float*)d_in[3];  // [256,256]
    const float* W1   = (const float*)d_in[4];  // [64,256]
    const float* a    = (const float*)d_in[5];  // [768,1]
    float* out = (float*)d_out;                 // [4,512,256]

    w1a3_kernel<<<2, 1024>>>(W1, a);
    mega_kernel<<<GEMM_CTAS + BB*NN, 256>>>(x, W, edge, a);
    softmax_av_kernel<<<BB*NN/TILE_I, 512>>>(adj, out);
}